// round 3
// baseline (speedup 1.0000x reference)
#include <cuda_runtime.h>

// Problem constants (fixed by the dataset)
#define NN 20000      // nodes
#define EE 320000     // edges
#define HH 256        // hidden dim (= D)
#define OO 10         // output dim
#define GG 64         // graphs
#define NBLK 120      // < #SMs on any Blackwell datacenter part -> co-resident
#define NTHR 256
#define NTOT (NBLK * NTHR)
#define PREBLK 11     // blocks 0..10 do weight precompute in phase 1

// ---------------- persistent scratch (no allocations allowed) ----------------
// Invariant: g_deg, g_ssum, g_acc, g_cnt are ZERO on kernel entry (zero at
// module load; re-zeroed at the end of every run). g_z/g_v1/g_M/g_c0 are
// fully overwritten each run.
__device__ float g_v1[HH];                         // emb[0] @ W1
__device__ __align__(16) float g_M[HH * 12];       // (W2 @ fcW), rows padded to 12
__device__ float g_c0[OO];                         // b2 @ fcW + fcb
__device__ int   g_deg[NN];                        // edge in-degree (excl self loop)
__device__ float g_ssum[NN];                       // sum of dis[src] over incoming edges
__device__ __align__(16) float g_z[NN * 12];       // per-node 10-vec, padded
__device__ float g_acc[GG * OO];
__device__ int   g_cnt[GG];

// grid barrier state
__device__ int          g_bar_count;
__device__ volatile int g_bar_gen;

__device__ __forceinline__ void grid_sync() {
    __threadfence();          // make this thread's global writes visible
    __syncthreads();
    if (threadIdx.x == 0) {
        int my = g_bar_gen;
        if (atomicAdd(&g_bar_count, 1) == NBLK - 1) {
            g_bar_count = 0;
            __threadfence();
            g_bar_gen = my + 1;
        } else {
            while (g_bar_gen == my) { __nanosleep(64); }
        }
        __threadfence();
    }
    __syncthreads();
}

__global__ void __launch_bounds__(NTHR, 1) gcn_fused(
    const int* __restrict__ src, const int* __restrict__ dst,
    const int* __restrict__ batch,
    const float* __restrict__ emb, const float* __restrict__ W1,
    const float* __restrict__ b1,  const float* __restrict__ W2,
    const float* __restrict__ b2,  const float* __restrict__ fcW,
    const float* __restrict__ fcb, float* __restrict__ out)
{
    __shared__ __align__(16) float sbuf[3584];   // 14 KB, reused across phases
    const int bid = blockIdx.x;
    const int t   = threadIdx.x;
    const int gtid = bid * NTHR + t;

    // ================= Phase 1: weight precompute  ||  deg + graph counts ====
    if (bid == 0) {
        // v1[t] = sum_d emb[d] * W1[d][t];  c0
        sbuf[t] = emb[t];
        __syncthreads();
        float acc = 0.f;
        #pragma unroll 8
        for (int d = 0; d < HH; d++) acc = fmaf(sbuf[d], W1[d * HH + t], acc);
        g_v1[t] = acc;
        if (t < OO) {
            float c = fcb[t];
            for (int k = 0; k < HH; k++) c = fmaf(b2[k], fcW[k * OO + t], c);
            g_c0[t] = c;
        }
    } else if (bid < PREBLK) {
        // column o of M = W2 @ fcW
        const int o = bid - 1;
        sbuf[t] = fcW[t * OO + o];
        __syncthreads();
        const float4* w2r = (const float4*)(W2 + t * HH);
        float acc = 0.f;
        #pragma unroll 8
        for (int k = 0; k < HH / 4; k++) {
            float4 w = w2r[k];
            acc = fmaf(w.x, sbuf[4 * k + 0], acc);
            acc = fmaf(w.y, sbuf[4 * k + 1], acc);
            acc = fmaf(w.z, sbuf[4 * k + 2], acc);
            acc = fmaf(w.w, sbuf[4 * k + 3], acc);
        }
        g_M[t * 12 + o] = acc;
    } else {
        const int lane0 = (bid - PREBLK) * NTHR + t;
        const int stride = (NBLK - PREBLK) * NTHR;
        for (int e = lane0; e < EE; e += stride) atomicAdd(&g_deg[dst[e]], 1);
        for (int i = lane0; i < NN; i += stride) atomicAdd(&g_cnt[batch[i]], 1);
    }
    grid_sync();

    // ================= Phase 2: ssum[dst] += dis[src] ========================
    for (int e = gtid; e < EE; e += NTOT) {
        int s = src[e];
        atomicAdd(&g_ssum[dst[e]], rsqrtf((float)(g_deg[s] + 1)));
    }
    grid_sync();

    // ================= Phase 3: z[i] = relu(s_i*v1 + b1) @ M =================
    // sbuf: [0,256) v1, [256,512) b1, [512,3584) M (padded 12/row)
    sbuf[t]       = g_v1[t];
    sbuf[256 + t] = b1[t];
    for (int j = t; j < HH * 12; j += NTHR) sbuf[512 + j] = g_M[j];
    __syncthreads();

    for (int i = gtid; i < NN; i += NTOT) {
        float dis = rsqrtf((float)(g_deg[i] + 1));
        float s   = dis * (dis + g_ssum[i]);
        float za[OO];
        #pragma unroll
        for (int o = 0; o < OO; o++) za[o] = 0.f;
        #pragma unroll 4
        for (int h = 0; h < HH; h++) {
            float v = fmaxf(fmaf(s, sbuf[h], sbuf[256 + h]), 0.f);
            const float4* mr = (const float4*)(sbuf + 512 + h * 12);
            float4 m0 = mr[0], m1 = mr[1], m2 = mr[2];
            za[0] = fmaf(v, m0.x, za[0]);
            za[1] = fmaf(v, m0.y, za[1]);
            za[2] = fmaf(v, m0.z, za[2]);
            za[3] = fmaf(v, m0.w, za[3]);
            za[4] = fmaf(v, m1.x, za[4]);
            za[5] = fmaf(v, m1.y, za[5]);
            za[6] = fmaf(v, m1.z, za[6]);
            za[7] = fmaf(v, m1.w, za[7]);
            za[8] = fmaf(v, m2.x, za[8]);
            za[9] = fmaf(v, m2.y, za[9]);
        }
        float4* zp = (float4*)(g_z + i * 12);
        zp[0] = make_float4(za[0], za[1], za[2], za[3]);
        zp[1] = make_float4(za[4], za[5], za[6], za[7]);
        zp[2] = make_float4(za[8], za[9], 0.f, 0.f);
    }
    grid_sync();

    // ================= Phase 4: edge aggregation into [G,O] ==================
    // 4 replicated smem accumulators (one per warp group of 4) to cut collisions
    for (int j = t; j < 4 * GG * OO; j += NTHR) sbuf[j] = 0.f;
    __syncthreads();
    {
        float* sa = sbuf + ((t >> 5) & 3) * (GG * OO);
        const int total = EE + NN;   // real edges + self loops
        for (int idx = gtid; idx < total; idx += NTOT) {
            int s, d;
            if (idx < EE) { s = src[idx]; d = dst[idx]; }
            else          { s = idx - EE; d = s; }
            float w = rsqrtf((float)(g_deg[s] + 1)) * rsqrtf((float)(g_deg[d] + 1));
            int g = batch[d];
            const float4* zp = (const float4*)(g_z + s * 12);
            float4 a = zp[0], b = zp[1], c = zp[2];
            float* base = sa + g * OO;
            atomicAdd(base + 0, w * a.x);
            atomicAdd(base + 1, w * a.y);
            atomicAdd(base + 2, w * a.z);
            atomicAdd(base + 3, w * a.w);
            atomicAdd(base + 4, w * b.x);
            atomicAdd(base + 5, w * b.y);
            atomicAdd(base + 6, w * b.z);
            atomicAdd(base + 7, w * b.w);
            atomicAdd(base + 8, w * c.x);
            atomicAdd(base + 9, w * c.y);
        }
    }
    __syncthreads();
    for (int j = t; j < GG * OO; j += NTHR) {
        float v = sbuf[j] + sbuf[640 + j] + sbuf[1280 + j] + sbuf[1920 + j];
        atomicAdd(&g_acc[j], v);
    }
    grid_sync();

    // ================= Phase 5: output + reset state for next run ============
    if (bid == 0) {
        for (int j = t; j < GG * OO; j += NTHR) {
            int g = j / OO, o = j - g * OO;
            out[j] = g_acc[j] / fmaxf((float)g_cnt[g], 1.f) + g_c0[o];
        }
        __syncthreads();
        for (int j = t; j < GG * OO; j += NTHR) g_acc[j] = 0.f;
        if (t < GG) g_cnt[t] = 0;
    }
    for (int i = gtid; i < NN; i += NTOT) {
        g_deg[i]  = 0;
        g_ssum[i] = 0.f;
    }
}

extern "C" void kernel_launch(void* const* d_in, const int* in_sizes, int n_in,
                              void* d_out, int out_size) {
    // metadata order: x, edge_index, batch, emb, W1, b1, W2, b2, fcW, fcb
    const int*   edge  = (const int*)d_in[1];
    const int*   src   = edge;
    const int*   dst   = edge + EE;
    const int*   batch = (const int*)d_in[2];
    const float* emb   = (const float*)d_in[3];
    const float* W1    = (const float*)d_in[4];
    const float* b1    = (const float*)d_in[5];
    const float* W2    = (const float*)d_in[6];
    const float* b2    = (const float*)d_in[7];
    const float* fcW   = (const float*)d_in[8];
    const float* fcb   = (const float*)d_in[9];
    float* out = (float*)d_out;

    gcn_fused<<<NBLK, NTHR>>>(src, dst, batch, emb, W1, b1, W2, b2, fcW, fcb, out);
}

// round 4
// speedup vs baseline: 1.4532x; 1.4532x over previous
#include <cuda_runtime.h>

// Problem constants (fixed by the dataset)
#define NN 20000      // nodes
#define EE 320000     // edges
#define HH 256        // hidden dim (= D)
#define OO 10         // output dim
#define GG 64         // graphs
#define NBLK 128      // <= SM count (148) at 1 block/SM -> co-resident guaranteed
#define NTHR 512
#define NTOT (NBLK * NTHR)
#define PREBLK 11     // blocks 0..10 do weight precompute in phase 1

// ---------------- persistent scratch (no allocations allowed) ----------------
// Invariant: g_deg, g_ssum, g_W, g_acc, g_cnt, g_done are ZERO on kernel entry
// (zero at module load; each phase that last consumes a buffer re-zeroes it).
__device__ float g_v1[HH];                         // emb[0] @ W1
__device__ __align__(16) float g_M[HH * 12];       // (W2 @ fcW), rows padded to 12
__device__ float g_c0[OO];                         // b2 @ fcW + fcb
__device__ int   g_deg[NN];                        // edge in-degree (excl self loop)
__device__ float g_ssum[NN];                       // sum of dis[src] over in-edges
__device__ float g_W[GG * NN];                     // W[g][s] = sum dis[dst] (+self)
__device__ __align__(16) float g_z[NN * 12];       // z'[s] = dis_s * (y_s @ M)
__device__ float g_acc[GG * OO];
__device__ int   g_cnt[GG];
__device__ int   g_done[GG];

// grid barrier state
__device__ int          g_bar_count;
__device__ volatile int g_bar_gen;

__device__ __forceinline__ void grid_sync() {
    __threadfence();
    __syncthreads();
    if (threadIdx.x == 0) {
        int my = g_bar_gen;
        if (atomicAdd(&g_bar_count, 1) == NBLK - 1) {
            g_bar_count = 0;
            __threadfence();
            g_bar_gen = my + 1;
        } else {
            while (g_bar_gen == my) { __nanosleep(64); }
        }
        __threadfence();
    }
    __syncthreads();
}

__global__ void __launch_bounds__(NTHR) gcn_fused(
    const int* __restrict__ src, const int* __restrict__ dst,
    const int* __restrict__ batch,
    const float* __restrict__ emb, const float* __restrict__ W1,
    const float* __restrict__ b1,  const float* __restrict__ W2,
    const float* __restrict__ b2,  const float* __restrict__ fcW,
    const float* __restrict__ fcb, float* __restrict__ out)
{
    __shared__ __align__(16) float sbuf[3584];   // 14 KB: phase 1 / phase 3 weights
    __shared__ float red[OO];
    __shared__ int   s_flag;
    const int bid  = blockIdx.x;
    const int t    = threadIdx.x;
    const int gtid = bid * NTHR + t;

    // ============ Phase 1: weight precompute || deg + per-graph counts =======
    if (bid == 0) {
        if (t < HH) sbuf[t] = emb[t];
        __syncthreads();
        if (t < HH) {
            float acc = 0.f;
            #pragma unroll 8
            for (int d = 0; d < HH; d++) acc = fmaf(sbuf[d], W1[d * HH + t], acc);
            g_v1[t] = acc;
        }
        if (t < OO) {
            float c = fcb[t];
            for (int k = 0; k < HH; k++) c = fmaf(b2[k], fcW[k * OO + t], c);
            g_c0[t] = c;
        }
    } else if (bid < PREBLK) {
        const int o = bid - 1;                 // column o of M = W2 @ fcW
        if (t < HH) sbuf[t] = fcW[t * OO + o];
        __syncthreads();
        if (t < HH) {
            const float4* w2r = (const float4*)(W2 + t * HH);
            float acc = 0.f;
            #pragma unroll 8
            for (int k = 0; k < HH / 4; k++) {
                float4 w = w2r[k];
                acc = fmaf(w.x, sbuf[4 * k + 0], acc);
                acc = fmaf(w.y, sbuf[4 * k + 1], acc);
                acc = fmaf(w.z, sbuf[4 * k + 2], acc);
                acc = fmaf(w.w, sbuf[4 * k + 3], acc);
            }
            g_M[t * 12 + o] = acc;
        }
    } else {
        const int lane0  = (bid - PREBLK) * NTHR + t;
        const int stride = (NBLK - PREBLK) * NTHR;
        #pragma unroll 2
        for (int e = lane0; e < EE; e += stride) atomicAdd(&g_deg[dst[e]], 1);
        for (int i = lane0; i < NN; i += stride) atomicAdd(&g_cnt[batch[i]], 1);
    }
    grid_sync();

    // ============ Phase 2: ssum[dst] += dis[src];  W[g(dst)][src] += dis[dst]
    #pragma unroll 2
    for (int e = gtid; e < EE; e += NTOT) {
        int s = src[e], d = dst[e];
        float dis_s = rsqrtf((float)(__ldg(&g_deg[s]) + 1));
        float dis_d = rsqrtf((float)(__ldg(&g_deg[d]) + 1));
        int   g     = __ldg(&batch[d]);
        atomicAdd(&g_ssum[d], dis_s);
        atomicAdd(&g_W[g * NN + s], dis_d);
    }
    grid_sync();

    // ============ Phase 3: z'[i] = dis_i * (relu(s_i*v1 + b1) @ M) ===========
    // sbuf: [0,256) v1, [256,512) b1, [512,3584) M (padded 12/row)
    if (t < HH) { sbuf[t] = g_v1[t]; sbuf[HH + t] = b1[t]; }
    for (int j = t; j < HH * 12; j += NTHR) sbuf[512 + j] = g_M[j];
    __syncthreads();

    for (int i = gtid; i < NN; i += NTOT) {
        int   deg  = g_deg[i];
        float ssum = g_ssum[i];
        float dis  = rsqrtf((float)(deg + 1));
        float sc   = dis * (dis + ssum);
        float za[OO];
        #pragma unroll
        for (int o = 0; o < OO; o++) za[o] = 0.f;
        #pragma unroll 4
        for (int h = 0; h < HH; h++) {
            float v = fmaxf(fmaf(sc, sbuf[h], sbuf[HH + h]), 0.f);
            const float4* mr = (const float4*)(sbuf + 512 + h * 12);
            float4 m0 = mr[0], m1 = mr[1], m2 = mr[2];
            za[0] = fmaf(v, m0.x, za[0]);
            za[1] = fmaf(v, m0.y, za[1]);
            za[2] = fmaf(v, m0.z, za[2]);
            za[3] = fmaf(v, m0.w, za[3]);
            za[4] = fmaf(v, m1.x, za[4]);
            za[5] = fmaf(v, m1.y, za[5]);
            za[6] = fmaf(v, m1.z, za[6]);
            za[7] = fmaf(v, m1.w, za[7]);
            za[8] = fmaf(v, m2.x, za[8]);
            za[9] = fmaf(v, m2.y, za[9]);
        }
        float4* zp = (float4*)(g_z + i * 12);
        zp[0] = make_float4(dis * za[0], dis * za[1], dis * za[2], dis * za[3]);
        zp[1] = make_float4(dis * za[4], dis * za[5], dis * za[6], dis * za[7]);
        zp[2] = make_float4(dis * za[8], dis * za[9], 0.f, 0.f);
        atomicAdd(&g_W[batch[i] * NN + i], dis);   // self loop
        g_deg[i]  = 0;                              // reset for next replay
        g_ssum[i] = 0.f;
    }
    grid_sync();

    // ============ Phase 4: out[g] = sum_s W[g][s] * z'[s]  (2 blocks/graph) ===
    {
        const int g    = bid >> 1;
        const int half = bid & 1;
        const int s0   = half * (NN / 2);
        const int s1   = s0 + (NN / 2);
        float za[OO];
        #pragma unroll
        for (int o = 0; o < OO; o++) za[o] = 0.f;
        if (t < OO) red[t] = 0.f;
        if (t == 0) s_flag = 0;
        __syncthreads();

        float* wrow = g_W + g * NN;
        for (int s = s0 + t; s < s1; s += NTHR) {
            float w = wrow[s];
            if (w != 0.f) {
                const float4* zp = (const float4*)(g_z + s * 12);
                float4 a = __ldg(zp), b = __ldg(zp + 1), c = __ldg(zp + 2);
                za[0] = fmaf(w, a.x, za[0]);
                za[1] = fmaf(w, a.y, za[1]);
                za[2] = fmaf(w, a.z, za[2]);
                za[3] = fmaf(w, a.w, za[3]);
                za[4] = fmaf(w, b.x, za[4]);
                za[5] = fmaf(w, b.y, za[5]);
                za[6] = fmaf(w, b.z, za[6]);
                za[7] = fmaf(w, b.w, za[7]);
                za[8] = fmaf(w, c.x, za[8]);
                za[9] = fmaf(w, c.y, za[9]);
                wrow[s] = 0.f;                      // reset for next replay
            }
        }
        // warp reduce, then per-warp smem atomics (16 warps x 10 = 160 ops)
        #pragma unroll
        for (int o = 0; o < OO; o++) {
            #pragma unroll
            for (int off = 16; off > 0; off >>= 1)
                za[o] += __shfl_down_sync(0xffffffffu, za[o], off);
        }
        if ((t & 31) == 0) {
            #pragma unroll
            for (int o = 0; o < OO; o++) atomicAdd(&red[o], za[o]);
        }
        __syncthreads();
        if (t < OO) atomicAdd(&g_acc[g * OO + t], red[t]);
        __threadfence();
        __syncthreads();
        if (t == 0) {
            if (atomicAdd(&g_done[g], 1) == 1) s_flag = 1;   // last of the pair
        }
        __syncthreads();
        if (s_flag && t < 32) {
            __threadfence();
            float inv = 1.f / fmaxf((float)g_cnt[g], 1.f);
            float o_val = 0.f;
            if (t < OO) {
                o_val = g_acc[g * OO + t] * inv + g_c0[t];
                out[g * OO + t] = o_val;
            }
            __syncwarp();
            if (t < OO) g_acc[g * OO + t] = 0.f;             // reset state
            if (t == 0) { g_cnt[g] = 0; g_done[g] = 0; }
        }
    }
}

extern "C" void kernel_launch(void* const* d_in, const int* in_sizes, int n_in,
                              void* d_out, int out_size) {
    // metadata order: x, edge_index, batch, emb, W1, b1, W2, b2, fcW, fcb
    const int*   edge  = (const int*)d_in[1];
    const int*   src   = edge;
    const int*   dst   = edge + EE;
    const int*   batch = (const int*)d_in[2];
    const float* emb   = (const float*)d_in[3];
    const float* W1    = (const float*)d_in[4];
    const float* b1    = (const float*)d_in[5];
    const float* W2    = (const float*)d_in[6];
    const float* b2    = (const float*)d_in[7];
    const float* fcW   = (const float*)d_in[8];
    const float* fcb   = (const float*)d_in[9];
    float* out = (float*)d_out;

    gcn_fused<<<NBLK, NTHR>>>(src, dst, batch, emb, W1, b1, W2, b2, fcW, fcb, out);
}

// round 5
// speedup vs baseline: 1.5360x; 1.0570x over previous
#include <cuda_runtime.h>

// Problem constants (fixed by the dataset)
#define NN 20000      // nodes
#define EE 320000     // edges
#define HH 256        // hidden dim (= D)
#define OO 10         // output dim
#define GG 64         // graphs
#define NBLK 384      // 148 SMs x 3 co-resident blocks = 444 max -> 384 safe
#define NTHR 512
#define NTOT (NBLK * NTHR)
#define PREBLK 11     // blocks 0..10 do weight precompute in phase 1
#define BPG (NBLK / GG)            // blocks per graph in phase 4 (= 6)
#define CHUNK ((NN + BPG - 1) / BPG)

// ---------------- persistent scratch (no allocations allowed) ----------------
// Invariant: g_deg, g_ssum, g_W, g_acc, g_cnt, g_done are ZERO on kernel entry
// (zero at module load; each phase that last consumes a buffer re-zeroes it).
__device__ float g_v1[HH];                         // emb[0] @ W1
__device__ __align__(16) float g_M[HH * 12];       // (W2 @ fcW), rows padded to 12
__device__ float g_c0[OO];                         // b2 @ fcW + fcb
__device__ int   g_deg[NN];                        // edge in-degree (excl self loop)
__device__ float g_ssum[NN];                       // sum of dis[src] over in-edges
__device__ float g_W[GG * NN];                     // W[g][s] = sum dis[dst] (+self)
__device__ __align__(16) float g_z[NN * 12];       // z'[s] = dis_s * (y_s @ M)
__device__ float g_acc[GG * OO];
__device__ int   g_cnt[GG];
__device__ int   g_done[GG];

// grid barrier state
__device__ int          g_bar_count;
__device__ volatile int g_bar_gen;

__device__ __forceinline__ void grid_sync() {
    __threadfence();
    __syncthreads();
    if (threadIdx.x == 0) {
        int my = g_bar_gen;
        if (atomicAdd(&g_bar_count, 1) == NBLK - 1) {
            g_bar_count = 0;
            __threadfence();
            g_bar_gen = my + 1;
        } else {
            while (g_bar_gen == my) { __nanosleep(32); }
        }
        __threadfence();
    }
    __syncthreads();
}

__global__ void __launch_bounds__(NTHR, 3) gcn_fused(
    const int* __restrict__ src, const int* __restrict__ dst,
    const int* __restrict__ batch,
    const float* __restrict__ emb, const float* __restrict__ W1,
    const float* __restrict__ b1,  const float* __restrict__ W2,
    const float* __restrict__ b2,  const float* __restrict__ fcW,
    const float* __restrict__ fcb, float* __restrict__ out)
{
    __shared__ __align__(16) float sbuf[3584];   // 14 KB: phase 1 / phase 3 weights
    __shared__ float red[OO];
    __shared__ int   s_flag;
    const int bid  = blockIdx.x;
    const int t    = threadIdx.x;
    const int gtid = bid * NTHR + t;

    // ============ Phase 1: weight precompute || deg + per-graph counts =======
    if (bid == 0) {
        if (t < HH) sbuf[t] = emb[t];
        __syncthreads();
        if (t < HH) {
            float acc = 0.f;
            #pragma unroll 8
            for (int d = 0; d < HH; d++) acc = fmaf(sbuf[d], W1[d * HH + t], acc);
            g_v1[t] = acc;
        }
        if (t < OO) {
            float c = fcb[t];
            for (int k = 0; k < HH; k++) c = fmaf(b2[k], fcW[k * OO + t], c);
            g_c0[t] = c;
        }
    } else if (bid < PREBLK) {
        const int o = bid - 1;                 // column o of M = W2 @ fcW
        if (t < HH) sbuf[t] = fcW[t * OO + o];
        __syncthreads();
        if (t < HH) {
            const float4* w2r = (const float4*)(W2 + t * HH);
            float acc = 0.f;
            #pragma unroll 8
            for (int k = 0; k < HH / 4; k++) {
                float4 w = w2r[k];
                acc = fmaf(w.x, sbuf[4 * k + 0], acc);
                acc = fmaf(w.y, sbuf[4 * k + 1], acc);
                acc = fmaf(w.z, sbuf[4 * k + 2], acc);
                acc = fmaf(w.w, sbuf[4 * k + 3], acc);
            }
            g_M[t * 12 + o] = acc;
        }
    } else {
        const int lane0  = (bid - PREBLK) * NTHR + t;
        const int stride = (NBLK - PREBLK) * NTHR;
        for (int e = lane0; e < EE; e += stride) atomicAdd(&g_deg[dst[e]], 1);
        for (int i = lane0; i < NN; i += stride) atomicAdd(&g_cnt[batch[i]], 1);
    }
    grid_sync();

    // ============ Phase 2: ssum[dst] += dis[src];  W[g(dst)][src] += dis[dst]
    for (int e = gtid; e < EE; e += NTOT) {
        int s = src[e], d = dst[e];
        float dis_s = rsqrtf((float)(__ldg(&g_deg[s]) + 1));
        float dis_d = rsqrtf((float)(__ldg(&g_deg[d]) + 1));
        int   g     = __ldg(&batch[d]);
        atomicAdd(&g_ssum[d], dis_s);
        atomicAdd(&g_W[g * NN + s], dis_d);
    }
    grid_sync();

    // ============ Phase 3: z'[i] = dis_i * (relu(s_i*v1 + b1) @ M) ===========
    // sbuf: [0,256) v1, [256,512) b1, [512,3584) M (padded 12/row)
    if (t < HH) { sbuf[t] = g_v1[t]; sbuf[HH + t] = b1[t]; }
    for (int j = t; j < HH * 12; j += NTHR) sbuf[512 + j] = g_M[j];
    __syncthreads();

    for (int i = gtid; i < NN; i += NTOT) {
        int   deg  = g_deg[i];
        float ssum = g_ssum[i];
        float dis  = rsqrtf((float)(deg + 1));
        float sc   = dis * (dis + ssum);
        float za[OO];
        #pragma unroll
        for (int o = 0; o < OO; o++) za[o] = 0.f;
        #pragma unroll 4
        for (int h = 0; h < HH; h++) {
            float v = fmaxf(fmaf(sc, sbuf[h], sbuf[HH + h]), 0.f);
            const float4* mr = (const float4*)(sbuf + 512 + h * 12);
            float4 m0 = mr[0], m1 = mr[1], m2 = mr[2];
            za[0] = fmaf(v, m0.x, za[0]);
            za[1] = fmaf(v, m0.y, za[1]);
            za[2] = fmaf(v, m0.z, za[2]);
            za[3] = fmaf(v, m0.w, za[3]);
            za[4] = fmaf(v, m1.x, za[4]);
            za[5] = fmaf(v, m1.y, za[5]);
            za[6] = fmaf(v, m1.z, za[6]);
            za[7] = fmaf(v, m1.w, za[7]);
            za[8] = fmaf(v, m2.x, za[8]);
            za[9] = fmaf(v, m2.y, za[9]);
        }
        float4* zp = (float4*)(g_z + i * 12);
        zp[0] = make_float4(dis * za[0], dis * za[1], dis * za[2], dis * za[3]);
        zp[1] = make_float4(dis * za[4], dis * za[5], dis * za[6], dis * za[7]);
        zp[2] = make_float4(dis * za[8], dis * za[9], 0.f, 0.f);
        atomicAdd(&g_W[batch[i] * NN + i], dis);   // self loop
        g_deg[i]  = 0;                              // reset for next replay
        g_ssum[i] = 0.f;
    }
    grid_sync();

    // ============ Phase 4: out[g] = sum_s W[g][s] * z'[s]  (BPG blocks/graph) =
    {
        const int g    = bid / BPG;
        const int part = bid - g * BPG;
        const int s0   = part * CHUNK;
        const int s1   = (s0 + CHUNK < NN) ? s0 + CHUNK : NN;
        float za[OO];
        #pragma unroll
        for (int o = 0; o < OO; o++) za[o] = 0.f;
        if (t < OO) red[t] = 0.f;
        if (t == 0) s_flag = 0;
        __syncthreads();

        float* wrow = g_W + g * NN;
        for (int s = s0 + t; s < s1; s += NTHR) {
            float w = wrow[s];
            if (w != 0.f) {
                const float4* zp = (const float4*)(g_z + s * 12);
                float4 a = __ldg(zp), b = __ldg(zp + 1), c = __ldg(zp + 2);
                za[0] = fmaf(w, a.x, za[0]);
                za[1] = fmaf(w, a.y, za[1]);
                za[2] = fmaf(w, a.z, za[2]);
                za[3] = fmaf(w, a.w, za[3]);
                za[4] = fmaf(w, b.x, za[4]);
                za[5] = fmaf(w, b.y, za[5]);
                za[6] = fmaf(w, b.z, za[6]);
                za[7] = fmaf(w, b.w, za[7]);
                za[8] = fmaf(w, c.x, za[8]);
                za[9] = fmaf(w, c.y, za[9]);
                wrow[s] = 0.f;                      // reset for next replay
            }
        }
        // warp reduce, then per-warp smem atomics (16 warps x 10 = 160 ops)
        #pragma unroll
        for (int o = 0; o < OO; o++) {
            #pragma unroll
            for (int off = 16; off > 0; off >>= 1)
                za[o] += __shfl_down_sync(0xffffffffu, za[o], off);
        }
        if ((t & 31) == 0) {
            #pragma unroll
            for (int o = 0; o < OO; o++) atomicAdd(&red[o], za[o]);
        }
        __syncthreads();
        if (t < OO) atomicAdd(&g_acc[g * OO + t], red[t]);
        __threadfence();
        __syncthreads();
        if (t == 0) {
            if (atomicAdd(&g_done[g], 1) == BPG - 1) s_flag = 1;  // last of group
        }
        __syncthreads();
        if (s_flag && t < 32) {
            __threadfence();
            float inv = 1.f / fmaxf((float)g_cnt[g], 1.f);
            if (t < OO) out[g * OO + t] = g_acc[g * OO + t] * inv + g_c0[t];
            __syncwarp();
            if (t < OO) g_acc[g * OO + t] = 0.f;                  // reset state
            if (t == 0) { g_cnt[g] = 0; g_done[g] = 0; }
        }
    }
}

extern "C" void kernel_launch(void* const* d_in, const int* in_sizes, int n_in,
                              void* d_out, int out_size) {
    // metadata order: x, edge_index, batch, emb, W1, b1, W2, b2, fcW, fcb
    const int*   edge  = (const int*)d_in[1];
    const int*   src   = edge;
    const int*   dst   = edge + EE;
    const int*   batch = (const int*)d_in[2];
    const float* emb   = (const float*)d_in[3];
    const float* W1    = (const float*)d_in[4];
    const float* b1    = (const float*)d_in[5];
    const float* W2    = (const float*)d_in[6];
    const float* b2    = (const float*)d_in[7];
    const float* fcW   = (const float*)d_in[8];
    const float* fcb   = (const float*)d_in[9];
    float* out = (float*)d_out;

    gcn_fused<<<NBLK, NTHR>>>(src, dst, batch, emb, W1, b1, W2, b2, fcW, fcb, out);
}

// round 6
// speedup vs baseline: 1.7675x; 1.1507x over previous
#include <cuda_runtime.h>

// Problem constants (fixed by the dataset)
#define NN 20000      // nodes
#define EE 320000     // edges
#define HH 256        // hidden dim (= D)
#define OO 10         // output dim
#define GG 64         // graphs
#define NBLK 384      // 148 SMs x 3 co-resident -> co-residency guaranteed
#define NTHR 512
#define NTOT (NBLK * NTHR)
#define PREBLK 11     // blocks 0..10: weight precompute in phase 1
#define ZBLK 40       // blocks 0..39 own the 20000 nodes in phase 3
#define BPG (NBLK / GG)        // 6 blocks per graph in phase 4
#define NN4 (NN / 4)           // 5000 float4 groups per W row
#define CHUNK4 ((NN4 + BPG - 1) / BPG)   // 834

// ---------------- persistent scratch (no allocations allowed) ----------------
// Invariant: g_deg, g_ssum, g_W, g_acc, g_done are ZERO on kernel entry
// (zero at module load; each replay re-zeroes what it dirtied).
__device__ float  g_v1[HH];                        // emb[0] @ W1
__device__ __align__(16) float g_M[HH * 12];       // (W2 @ fcW), rows padded to 12
__device__ float  g_c0[OO];                        // b2 @ fcW + fcb
__device__ float  g_inv[GG];                       // 1 / max(cnt_g, 1)
__device__ int    g_deg[NN];                       // in-degree excl self loop
__device__ float  g_ssum[NN];                      // sum of dis[src] over in-edges
__device__ float2 g_dd[NN];                        // {dis_i, batch_i-as-float-bits}
__device__ float  g_W[GG * NN];                    // W[g][s] = sum dis_dst (+self)
__device__ __align__(16) float g_z[NN * 12];       // z'[s] = dis_s * (y_s @ M)
__device__ float  g_acc[GG * OO];
__device__ int    g_done[GG];

// grid barrier state
__device__ int          g_bar_count;
__device__ volatile int g_bar_gen;

__device__ __forceinline__ void grid_sync() {
    __threadfence();
    __syncthreads();
    if (threadIdx.x == 0) {
        int my = g_bar_gen;
        if (atomicAdd(&g_bar_count, 1) == NBLK - 1) {
            g_bar_count = 0;
            __threadfence();
            g_bar_gen = my + 1;
        } else {
            while (g_bar_gen == my) { __nanosleep(20); }
        }
        __threadfence();
    }
    __syncthreads();
}

__device__ __forceinline__ int lower_bound_batch(const int* __restrict__ batch, int key) {
    int lo = 0, hi = NN;
    while (lo < hi) {
        int mid = (lo + hi) >> 1;
        if (__ldg(&batch[mid]) < key) lo = mid + 1; else hi = mid;
    }
    return lo;
}

__global__ void __launch_bounds__(NTHR, 3) gcn_fused(
    const int* __restrict__ src, const int* __restrict__ dst,
    const int* __restrict__ batch,
    const float* __restrict__ emb, const float* __restrict__ W1,
    const float* __restrict__ b1,  const float* __restrict__ W2,
    const float* __restrict__ b2,  const float* __restrict__ fcW,
    const float* __restrict__ fcb, float* __restrict__ out)
{
    __shared__ __align__(16) float sbuf[3584];   // 14 KB (phase 1 / phase 3)
    __shared__ float red[OO];
    __shared__ int   s_flag;
    const int bid  = blockIdx.x;
    const int t    = threadIdx.x;
    const int gtid = bid * NTHR + t;

    // ===== Phase 1: weight precompute || deg atomics || cnt binary search ====
    if (bid == 0) {
        if (t < HH) sbuf[t] = emb[t];
        __syncthreads();
        if (t < HH) {                      // v1
            float acc = 0.f;
            #pragma unroll 8
            for (int d = 0; d < HH; d++) acc = fmaf(sbuf[d], W1[d * HH + t], acc);
            g_v1[t] = acc;
        } else if (t < HH + GG) {          // per-graph inverse counts (sorted batch)
            int g  = t - HH;
            int lo = lower_bound_batch(batch, g);
            int hi = lower_bound_batch(batch, g + 1);
            g_inv[g] = 1.f / fmaxf((float)(hi - lo), 1.f);
        } else if (t < HH + GG + OO) {     // c0
            int o = t - HH - GG;
            float c = fcb[o];
            for (int k = 0; k < HH; k++) c = fmaf(b2[k], fcW[k * OO + o], c);
            g_c0[o] = c;
        }
    } else if (bid < PREBLK) {
        const int o = bid - 1;             // column o of M = W2 @ fcW
        if (t < HH) sbuf[t] = fcW[t * OO + o];
        __syncthreads();
        if (t < HH) {
            const float4* w2r = (const float4*)(W2 + t * HH);
            float acc = 0.f;
            #pragma unroll 8
            for (int k = 0; k < HH / 4; k++) {
                float4 w = w2r[k];
                acc = fmaf(w.x, sbuf[4 * k + 0], acc);
                acc = fmaf(w.y, sbuf[4 * k + 1], acc);
                acc = fmaf(w.z, sbuf[4 * k + 2], acc);
                acc = fmaf(w.w, sbuf[4 * k + 3], acc);
            }
            g_M[t * 12 + o] = acc;
        }
    } else {
        const int lane0  = (bid - PREBLK) * NTHR + t;
        const int stride = (NBLK - PREBLK) * NTHR;
        for (int e = lane0; e < EE; e += stride) atomicAdd(&g_deg[dst[e]], 1);
    }
    grid_sync();

    // ===== Phase 2: ssum[dst] += dis[src];  publish g_dd[i] = {dis_i, batch_i}
    if (gtid < NN) {
        float dis = rsqrtf((float)(g_deg[gtid] + 1));
        g_dd[gtid] = make_float2(dis, __int_as_float(__ldg(&batch[gtid])));
    }
    for (int e = gtid; e < EE; e += NTOT) {
        int s = src[e], d = dst[e];
        atomicAdd(&g_ssum[d], rsqrtf((float)(__ldg(&g_deg[s]) + 1)));
    }
    grid_sync();

    // ===== Phase 3: z' compute (blocks < ZBLK)  ||  W edge atomics (rest) ====
    if (bid < ZBLK) {
        // sbuf: [0,256) v1, [256,512) b1, [512,3584) M (padded 12/row)
        if (t < HH) { sbuf[t] = g_v1[t]; sbuf[HH + t] = b1[t]; }
        for (int j = t; j < HH * 12; j += NTHR) sbuf[512 + j] = g_M[j];
        __syncthreads();

        const int i = gtid;                // exactly one node per thread
        if (i < NN) {
            float2 dd  = g_dd[i];
            float  dis = dd.x;
            float  sc  = dis * (dis + g_ssum[i]);
            float za[OO];
            #pragma unroll
            for (int o = 0; o < OO; o++) za[o] = 0.f;
            #pragma unroll 4
            for (int h = 0; h < HH; h++) {
                float v = fmaxf(fmaf(sc, sbuf[h], sbuf[HH + h]), 0.f);
                const float4* mr = (const float4*)(sbuf + 512 + h * 12);
                float4 m0 = mr[0], m1 = mr[1], m2 = mr[2];
                za[0] = fmaf(v, m0.x, za[0]);
                za[1] = fmaf(v, m0.y, za[1]);
                za[2] = fmaf(v, m0.z, za[2]);
                za[3] = fmaf(v, m0.w, za[3]);
                za[4] = fmaf(v, m1.x, za[4]);
                za[5] = fmaf(v, m1.y, za[5]);
                za[6] = fmaf(v, m1.z, za[6]);
                za[7] = fmaf(v, m1.w, za[7]);
                za[8] = fmaf(v, m2.x, za[8]);
                za[9] = fmaf(v, m2.y, za[9]);
            }
            float4* zp = (float4*)(g_z + i * 12);
            zp[0] = make_float4(dis * za[0], dis * za[1], dis * za[2], dis * za[3]);
            zp[1] = make_float4(dis * za[4], dis * za[5], dis * za[6], dis * za[7]);
            zp[2] = make_float4(dis * za[8], dis * za[9], 0.f, 0.f);
            atomicAdd(&g_W[__float_as_int(dd.y) * NN + i], dis);   // self loop
        }
    } else {
        const int lane0  = (bid - ZBLK) * NTHR + t;
        const int stride = (NBLK - ZBLK) * NTHR;
        for (int e = lane0; e < EE; e += stride) {
            int s = src[e], d = dst[e];
            float2 dd = __ldg(&g_dd[d]);                // {dis_d, batch_d}
            atomicAdd(&g_W[__float_as_int(dd.y) * NN + s], dd.x);
        }
    }
    grid_sync();

    // ===== Phase 4: out[g] = sum_s W[g][s]*z'[s]  (BPG blocks/graph, float4) ==
    {
        // reset deg/ssum for next replay (safe now: nothing reads them anymore)
        if (gtid < NN) { g_deg[gtid] = 0; g_ssum[gtid] = 0.f; }

        const int g    = bid / BPG;
        const int part = bid - g * BPG;
        const int j0   = part * CHUNK4;
        const int j1   = (j0 + CHUNK4 < NN4) ? j0 + CHUNK4 : NN4;
        float za[OO];
        #pragma unroll
        for (int o = 0; o < OO; o++) za[o] = 0.f;
        if (t < OO) red[t] = 0.f;
        if (t == 0) s_flag = 0;
        __syncthreads();

        float4* wrow4 = (float4*)(g_W + g * NN);
        const float4 zero4 = make_float4(0.f, 0.f, 0.f, 0.f);
        for (int j = j0 + t; j < j1; j += NTHR) {
            float4 w4 = wrow4[j];
            wrow4[j] = zero4;                            // reset for next replay
            #pragma unroll
            for (int q = 0; q < 4; q++) {
                float w = (q == 0) ? w4.x : (q == 1) ? w4.y : (q == 2) ? w4.z : w4.w;
                if (w != 0.f) {
                    const float4* zp = (const float4*)(g_z + (4 * j + q) * 12);
                    float4 a = __ldg(zp), b = __ldg(zp + 1), c = __ldg(zp + 2);
                    za[0] = fmaf(w, a.x, za[0]);
                    za[1] = fmaf(w, a.y, za[1]);
                    za[2] = fmaf(w, a.z, za[2]);
                    za[3] = fmaf(w, a.w, za[3]);
                    za[4] = fmaf(w, b.x, za[4]);
                    za[5] = fmaf(w, b.y, za[5]);
                    za[6] = fmaf(w, b.z, za[6]);
                    za[7] = fmaf(w, b.w, za[7]);
                    za[8] = fmaf(w, c.x, za[8]);
                    za[9] = fmaf(w, c.y, za[9]);
                }
            }
        }
        #pragma unroll
        for (int o = 0; o < OO; o++) {
            #pragma unroll
            for (int off = 16; off > 0; off >>= 1)
                za[o] += __shfl_down_sync(0xffffffffu, za[o], off);
        }
        if ((t & 31) == 0) {
            #pragma unroll
            for (int o = 0; o < OO; o++) atomicAdd(&red[o], za[o]);
        }
        __syncthreads();
        if (t < OO) atomicAdd(&g_acc[g * OO + t], red[t]);
        __threadfence();
        __syncthreads();
        if (t == 0) {
            if (atomicAdd(&g_done[g], 1) == BPG - 1) s_flag = 1;  // last of group
        }
        __syncthreads();
        if (s_flag && t < 32) {
            __threadfence();
            float inv = g_inv[g];
            if (t < OO) out[g * OO + t] = g_acc[g * OO + t] * inv + g_c0[t];
            __syncwarp();
            if (t < OO) g_acc[g * OO + t] = 0.f;                  // reset state
            if (t == 0) g_done[g] = 0;
        }
    }
}

extern "C" void kernel_launch(void* const* d_in, const int* in_sizes, int n_in,
                              void* d_out, int out_size) {
    // metadata order: x, edge_index, batch, emb, W1, b1, W2, b2, fcW, fcb
    const int*   edge  = (const int*)d_in[1];
    const int*   src   = edge;
    const int*   dst   = edge + EE;
    const int*   batch = (const int*)d_in[2];
    const float* emb   = (const float*)d_in[3];
    const float* W1    = (const float*)d_in[4];
    const float* b1    = (const float*)d_in[5];
    const float* W2    = (const float*)d_in[6];
    const float* b2    = (const float*)d_in[7];
    const float* fcW   = (const float*)d_in[8];
    const float* fcb   = (const float*)d_in[9];
    float* out = (float*)d_out;

    gcn_fused<<<NBLK, NTHR>>>(src, dst, batch, emb, W1, b1, W2, b2, fcW, fcb, out);
}